// round 1
// baseline (speedup 1.0000x reference)
#include <cuda_runtime.h>
#include <cuda_bf16.h>

#define N_SRC   100000
#define N_TGT   50000
#define N_EDGES 600000
#define CH      128
#define NREL    7
#define NTYP    4

// Scratch (allocation-free rule: __device__ globals)
__device__ float g_agg[(size_t)N_TGT * NREL * CH];   // per (dst, rel) feature sums
__device__ float g_cnt[N_TGT * NREL];                // per (dst, rel) edge counts

// ---------------------------------------------------------------------------
// Kernel 1: edge scatter. One warp per edge: gather x_src row (float4/lane),
// atomicAdd into agg[dst][rel][*]; lane 0 bumps the count.
// ---------------------------------------------------------------------------
__global__ __launch_bounds__(256) void scatter_kernel(
    const float* __restrict__ xs,
    const int* __restrict__ esrc,
    const int* __restrict__ edst,
    const int* __restrict__ etyp,
    float* __restrict__ agg,
    float* __restrict__ cnt)
{
    int w = (blockIdx.x * 256 + threadIdx.x) >> 5;
    int lane = threadIdx.x & 31;
    if (w >= N_EDGES) return;
    int s = esrc[w];
    int d = edst[w];
    int t = etyp[w];
    float4 v = ((const float4*)(xs + ((size_t)s << 7)))[lane];
    float* base = agg + (((size_t)d * NREL + t) << 7) + (lane << 2);
    atomicAdd(base + 0, v.x);
    atomicAdd(base + 1, v.y);
    atomicAdd(base + 2, v.z);
    atomicAdd(base + 3, v.w);
    if (lane == 0) atomicAdd(cnt + d * NREL + t, 1.0f);
}

// ---------------------------------------------------------------------------
// Kernel 2: fused GEMM.
//   out[g][c] = sum_r (agg[g][r][:] / max(cnt[g][r],1)) . rel_w[r][c][:]
//            +  x_target[g][:] . root_w[type[g]][c][:]  +  root_b[type[g]][c]
// Tile: 64 rows x 128 cols per 256-thread block; 8x4 register tile per thread.
// smem B layout: [c][kk] stride 33 -> conflict-free scalar LDS on both sides.
// ---------------------------------------------------------------------------
#define SB_STRIDE 33
#define SB_PER_MAT (128 * SB_STRIDE)   // 4224 floats per 128c x 32kk tile

__global__ __launch_bounds__(256) void gemm_kernel(
    const float* __restrict__ agg,
    const float* __restrict__ cnt,
    const float* __restrict__ relw,   // (7,128,128)
    const float* __restrict__ xt,     // (50000,128)
    const float* __restrict__ rootw,  // (4,128,128)
    const float* __restrict__ rootb,  // (4,128)
    const int*   __restrict__ ttype,  // (50000,)
    float* __restrict__ out)
{
    extern __shared__ float sm[];
    float* sB   = sm;                         // 4 * 4224 floats (root uses all 4)
    float* sA   = sm + 4 * SB_PER_MAT;        // 64 * 33 = 2112
    float* sInv = sA + 64 * SB_STRIDE;        // 64 * 7 = 448
    int*   sTyp = (int*)(sInv + 64 * NREL);   // 64

    const int tid = threadIdx.x;
    const int tr = tid >> 5;       // warp id 0..7 -> rows tr*8 .. tr*8+7
    const int tc = tid & 31;       // cols tc, tc+32, tc+64, tc+96
    const int row0 = blockIdx.x * 64;

    // Prologue: inverse counts + node types for this row tile
    for (int i = tid; i < 64 * NREL; i += 256) {
        int row = i / NREL, r = i - row * NREL;
        int g = row0 + row;
        float c = (g < N_TGT) ? cnt[g * NREL + r] : 1.0f;
        sInv[row * NREL + r] = 1.0f / fmaxf(c, 1.0f);
    }
    if (tid < 64) {
        int g = row0 + tid;
        sTyp[tid] = (g < N_TGT) ? ttype[g] : 0;
    }

    float acc[8][4];
#pragma unroll
    for (int i = 0; i < 8; ++i)
#pragma unroll
        for (int j = 0; j < 4; ++j) acc[i][j] = 0.0f;

    // ---- relation segments: K = 7 * 128 ----
    for (int r = 0; r < NREL; ++r) {
        for (int k0 = 0; k0 < CH; k0 += 32) {
            __syncthreads();
            // A tile: 64 rows x 32 kk (normalized). 512 float4 / 256 thr.
            for (int i = tid; i < 512; i += 256) {
                int row = i >> 3, kv = i & 7;
                int g = row0 + row;
                float4 v = make_float4(0.f, 0.f, 0.f, 0.f);
                if (g < N_TGT)
                    v = *(const float4*)(agg + (((size_t)g * NREL + r) << 7) + k0 + (kv << 2));
                float inv = sInv[row * NREL + r];
                float* dp = sA + row * SB_STRIDE + (kv << 2);
                dp[0] = v.x * inv; dp[1] = v.y * inv; dp[2] = v.z * inv; dp[3] = v.w * inv;
            }
            // B tile: 128 c x 32 kk -> sB[c*33 + kk]. 1024 float4 / 256 thr.
            for (int i = tid; i < 1024; i += 256) {
                int c = i >> 3, kv = i & 7;
                float4 v = *(const float4*)(relw + (((r << 7) + c) << 7) + k0 + (kv << 2));
                float* dp = sB + c * SB_STRIDE + (kv << 2);
                dp[0] = v.x; dp[1] = v.y; dp[2] = v.z; dp[3] = v.w;
            }
            __syncthreads();
#pragma unroll 4
            for (int kk = 0; kk < 32; ++kk) {
                float b0 = sB[(tc      ) * SB_STRIDE + kk];
                float b1 = sB[(tc + 32 ) * SB_STRIDE + kk];
                float b2 = sB[(tc + 64 ) * SB_STRIDE + kk];
                float b3 = sB[(tc + 96 ) * SB_STRIDE + kk];
#pragma unroll
                for (int i = 0; i < 8; ++i) {
                    float a = sA[(tr * 8 + i) * SB_STRIDE + kk];
                    acc[i][0] += a * b0;
                    acc[i][1] += a * b1;
                    acc[i][2] += a * b2;
                    acc[i][3] += a * b3;
                }
            }
        }
    }

    // ---- root segment: K = 128, per-row type-selected B ----
    for (int k0 = 0; k0 < CH; k0 += 32) {
        __syncthreads();
        // A tile: x_target
        for (int i = tid; i < 512; i += 256) {
            int row = i >> 3, kv = i & 7;
            int g = row0 + row;
            float4 v = make_float4(0.f, 0.f, 0.f, 0.f);
            if (g < N_TGT)
                v = *(const float4*)(xt + ((size_t)g << 7) + k0 + (kv << 2));
            float* dp = sA + row * SB_STRIDE + (kv << 2);
            dp[0] = v.x; dp[1] = v.y; dp[2] = v.z; dp[3] = v.w;
        }
        // All 4 root weight chunks: 4 * 1024 float4 / 256 thr.
        for (int i = tid; i < 4096; i += 256) {
            int t = i >> 10, c = (i >> 3) & 127, kv = i & 7;
            float4 v = *(const float4*)(rootw + (((t << 7) + c) << 7) + k0 + (kv << 2));
            float* dp = sB + t * SB_PER_MAT + c * SB_STRIDE + (kv << 2);
            dp[0] = v.x; dp[1] = v.y; dp[2] = v.z; dp[3] = v.w;
        }
        __syncthreads();
#pragma unroll
        for (int i = 0; i < 8; ++i) {
            int row = tr * 8 + i;
            const float* bp = sB + sTyp[row] * SB_PER_MAT;   // uniform across warp
#pragma unroll 4
            for (int kk = 0; kk < 32; ++kk) {
                float a = sA[row * SB_STRIDE + kk];
                acc[i][0] += a * bp[(tc      ) * SB_STRIDE + kk];
                acc[i][1] += a * bp[(tc + 32 ) * SB_STRIDE + kk];
                acc[i][2] += a * bp[(tc + 64 ) * SB_STRIDE + kk];
                acc[i][3] += a * bp[(tc + 96 ) * SB_STRIDE + kk];
            }
        }
    }

    // ---- epilogue: + bias, store ----
#pragma unroll
    for (int i = 0; i < 8; ++i) {
        int row = tr * 8 + i;
        int g = row0 + row;
        if (g < N_TGT) {
            int t = sTyp[row];
#pragma unroll
            for (int j = 0; j < 4; ++j) {
                int c = tc + 32 * j;
                out[((size_t)g << 7) + c] = acc[i][j] + rootb[(t << 7) + c];
            }
        }
    }
}

extern "C" void kernel_launch(void* const* d_in, const int* in_sizes, int n_in,
                              void* d_out, int out_size)
{
    const float* x_src  = (const float*)d_in[0];
    const float* x_tgt  = (const float*)d_in[1];
    const float* rel_w  = (const float*)d_in[2];
    const float* root_w = (const float*)d_in[3];
    const float* root_b = (const float*)d_in[4];
    const int*   e_src  = (const int*)d_in[5];
    const int*   e_dst  = (const int*)d_in[6];
    const int*   e_typ  = (const int*)d_in[7];
    const int*   n_typ  = (const int*)d_in[8];
    float* out = (float*)d_out;

    void *aggp = nullptr, *cntp = nullptr;
    cudaGetSymbolAddress(&aggp, g_agg);
    cudaGetSymbolAddress(&cntp, g_cnt);
    cudaMemsetAsync(aggp, 0, (size_t)N_TGT * NREL * CH * sizeof(float));
    cudaMemsetAsync(cntp, 0, (size_t)N_TGT * NREL * sizeof(float));

    scatter_kernel<<<N_EDGES / 8, 256>>>(x_src, e_src, e_dst, e_typ,
                                         (float*)aggp, (float*)cntp);

    int smem_bytes = (4 * SB_PER_MAT + 64 * SB_STRIDE + 64 * NREL) * (int)sizeof(float)
                   + 64 * (int)sizeof(int);
    cudaFuncSetAttribute(gemm_kernel, cudaFuncAttributeMaxDynamicSharedMemorySize, smem_bytes);
    gemm_kernel<<<(N_TGT + 63) / 64, 256, smem_bytes>>>(
        (const float*)aggp, (const float*)cntp, rel_w, x_tgt, root_w, root_b, n_typ, out);
}

// round 4
// speedup vs baseline: 2.8292x; 2.8292x over previous
#include <cuda_runtime.h>
#include <cstdint>

#define N_SRC   100000
#define N_TGT   50000
#define N_EDGES 600000
#define CH      128
#define NREL    7
#define NTYP    4
#define NSEG    11          // 7 relation segments + 4 masked root segments
#define NCHUNK  44          // NSEG * (128/32)

// Scratch (allocation-free rule: __device__ globals)
__device__ float g_agg[(size_t)N_TGT * NREL * CH];
__device__ float g_cnt[N_TGT * NREL];

__device__ __forceinline__ uint32_t to_tf32(float x) {
    uint32_t r;
    asm("cvt.rna.tf32.f32 %0, %1;" : "=r"(r) : "f"(x));
    return r;
}

__device__ __forceinline__ void mma_tf32(float* c,
    uint32_t a0, uint32_t a1, uint32_t a2, uint32_t a3,
    uint32_t b0, uint32_t b1)
{
    asm volatile(
        "mma.sync.aligned.m16n8k8.row.col.f32.tf32.tf32.f32 "
        "{%0,%1,%2,%3}, {%4,%5,%6,%7}, {%8,%9}, {%0,%1,%2,%3};"
        : "+f"(c[0]), "+f"(c[1]), "+f"(c[2]), "+f"(c[3])
        : "r"(a0), "r"(a1), "r"(a2), "r"(a3), "r"(b0), "r"(b1));
}

// ---------------- kernel 1: edge scatter ----------------
__global__ __launch_bounds__(256) void scatter_kernel(
    const float* __restrict__ xs,
    const int* __restrict__ esrc, const int* __restrict__ edst,
    const int* __restrict__ etyp,
    float* __restrict__ agg, float* __restrict__ cnt)
{
    int w = (blockIdx.x * 256 + threadIdx.x) >> 5;
    int lane = threadIdx.x & 31;
    if (w >= N_EDGES) return;
    int s = __ldg(esrc + w);
    int d = __ldg(edst + w);
    int t = __ldg(etyp + w);
    float4 v = ((const float4*)(xs + ((size_t)s << 7)))[lane];
    float* base = agg + (((size_t)d * NREL + t) << 7) + (lane << 2);
    asm volatile("red.global.add.v4.f32 [%0], {%1,%2,%3,%4};"
                 :: "l"(base), "f"(v.x), "f"(v.y), "f"(v.z), "f"(v.w) : "memory");
    if (lane == 0)
        asm volatile("red.global.add.f32 [%0], %1;"
                     :: "l"(cnt + d * NREL + t), "f"(1.0f) : "memory");
}

// ---------------- kernel 2: tf32 mma.sync fused GEMM ----------------
// out[g][c] = sum_{r<7} (agg[g][r]/max(cnt,1)) . rel_w[r][c]
//           + x_target[g] . root_w[type[g]][c] + root_b[type[g]][c]
// CTA: 128 rows x 128 cols. 8 warps in 2x4 grid -> 64x32 per warp,
// 4x4 m16n8k8 tiles. Stride-36 smem: fragment LDS conflict-free.
#define SSTR 36

__global__ __launch_bounds__(256, 1) void gemm_mma_kernel(
    const float* __restrict__ agg, const float* __restrict__ cnt,
    const float* __restrict__ relw, const float* __restrict__ xt,
    const float* __restrict__ rootw, const float* __restrict__ rootb,
    const int* __restrict__ ttype, float* __restrict__ out)
{
    __shared__ uint32_t sA[128 * SSTR];
    __shared__ uint32_t sB[128 * SSTR];
    __shared__ float    sInv[128 * NREL];
    __shared__ int      sTyp[128];

    const int tid = threadIdx.x;
    const int wid = tid >> 5;
    const int lid = tid & 31;
    const int wm = wid & 1;         // row half: 0/1 -> rows wm*64..
    const int wn = wid >> 1;        // col quarter: 0..3 -> cols wn*32..
    const int row0 = blockIdx.x * 128;

    for (int i = tid; i < 128 * NREL; i += 256) {
        int row = i / NREL, r = i - row * NREL;
        int g = row0 + row;
        float c = (g < N_TGT) ? cnt[g * NREL + r] : 1.0f;
        sInv[i] = 1.0f / fmaxf(c, 1.0f);
    }
    if (tid < 128) {
        int g = row0 + tid;
        sTyp[tid] = (g < N_TGT) ? ttype[g] : -1;
    }
    __syncthreads();

    float acc[4][4][4];
#pragma unroll
    for (int mi = 0; mi < 4; ++mi)
#pragma unroll
        for (int ni = 0; ni < 4; ++ni)
#pragma unroll
            for (int q = 0; q < 4; ++q) acc[mi][ni][q] = 0.0f;

    float4 ra[4], rb[4];
    auto load_chunk = [&](int ci) {
        int seg = ci >> 2;
        int k0  = (ci & 3) << 5;
#pragma unroll
        for (int j = 0; j < 4; ++j) {
            int f = tid + (j << 8);          // 0..1023
            int row = f >> 3, kv = f & 7;
            int g = row0 + row;
            float4 v = make_float4(0.f, 0.f, 0.f, 0.f);
            if (seg < NREL) {
                if (g < N_TGT)
                    v = *(const float4*)(agg + (((size_t)g * NREL + seg) << 7) + k0 + (kv << 2));
            } else {
                if (g < N_TGT && sTyp[row] == seg - NREL)
                    v = *(const float4*)(xt + ((size_t)g << 7) + k0 + (kv << 2));
            }
            ra[j] = v;
        }
#pragma unroll
        for (int j = 0; j < 4; ++j) {
            int f = tid + (j << 8);
            int c = f >> 3, kv = f & 7;
            const float* wp = (seg < NREL)
                ? relw  + (((size_t)((seg << 7) + c)) << 7)
                : rootw + (((size_t)(((seg - NREL) << 7) + c)) << 7);
            rb[j] = *(const float4*)(wp + k0 + (kv << 2));
        }
    };
    auto store_chunk = [&](int ci) {
        int seg = ci >> 2;
#pragma unroll
        for (int j = 0; j < 4; ++j) {
            int f = tid + (j << 8);
            int row = f >> 3, kv = f & 7;
            float4 v = ra[j];
            if (seg < NREL) {
                float inv = sInv[row * NREL + seg];
                v.x *= inv; v.y *= inv; v.z *= inv; v.w *= inv;
            }
            uint4 w;
            w.x = to_tf32(v.x); w.y = to_tf32(v.y);
            w.z = to_tf32(v.z); w.w = to_tf32(v.w);
            *(uint4*)(sA + row * SSTR + (kv << 2)) = w;
        }
#pragma unroll
        for (int j = 0; j < 4; ++j) {
            int f = tid + (j << 8);
            int c = f >> 3, kv = f & 7;
            float4 v = rb[j];
            uint4 w;
            w.x = to_tf32(v.x); w.y = to_tf32(v.y);
            w.z = to_tf32(v.z); w.w = to_tf32(v.w);
            *(uint4*)(sB + c * SSTR + (kv << 2)) = w;
        }
    };

    const uint32_t* pA = sA + ((wm << 6) + (lid >> 2)) * SSTR;
    const uint32_t* pB = sB + ((wn << 5) + (lid >> 2)) * SSTR;

    load_chunk(0);
    for (int ci = 0; ci < NCHUNK; ++ci) {
        __syncthreads();               // previous compute done; smem reusable
        store_chunk(ci);
        if (ci + 1 < NCHUNK) load_chunk(ci + 1);   // LDG overlaps compute
        __syncthreads();               // chunk visible
#pragma unroll
        for (int ks = 0; ks < 4; ++ks) {
            int kk = (ks << 3) + (lid & 3);
            uint32_t b[4][2];
#pragma unroll
            for (int ni = 0; ni < 4; ++ni) {
                b[ni][0] = pB[(ni << 3) * SSTR + kk];
                b[ni][1] = pB[(ni << 3) * SSTR + kk + 4];
            }
#pragma unroll
            for (int mi = 0; mi < 4; ++mi) {
                // PTX m16n8k8.tf32 A-fragment order: (r,k), (r+8,k), (r,k+4), (r+8,k+4)
                uint32_t a0 = pA[(mi << 4) * SSTR + kk];
                uint32_t a1 = pA[((mi << 4) + 8) * SSTR + kk];
                uint32_t a2 = pA[(mi << 4) * SSTR + kk + 4];
                uint32_t a3 = pA[((mi << 4) + 8) * SSTR + kk + 4];
#pragma unroll
                for (int ni = 0; ni < 4; ++ni)
                    mma_tf32(acc[mi][ni], a0, a1, a2, a3, b[ni][0], b[ni][1]);
            }
        }
    }

    // ---- epilogue: bias + store (float2 per accum pair) ----
#pragma unroll
    for (int mi = 0; mi < 4; ++mi) {
#pragma unroll
        for (int half = 0; half < 2; ++half) {
            int row = (wm << 6) + (mi << 4) + (half << 3) + (lid >> 2);
            int g = row0 + row;
            if (g >= N_TGT) continue;
            int t = sTyp[row];
#pragma unroll
            for (int ni = 0; ni < 4; ++ni) {
                int col = (wn << 5) + (ni << 3) + ((lid & 3) << 1);
                float2 o;
                o.x = acc[mi][ni][half * 2 + 0] + rootb[(t << 7) + col];
                o.y = acc[mi][ni][half * 2 + 1] + rootb[(t << 7) + col + 1];
                *(float2*)(out + ((size_t)g << 7) + col) = o;
            }
        }
    }
}

extern "C" void kernel_launch(void* const* d_in, const int* in_sizes, int n_in,
                              void* d_out, int out_size)
{
    const float* x_src  = (const float*)d_in[0];
    const float* x_tgt  = (const float*)d_in[1];
    const float* rel_w  = (const float*)d_in[2];
    const float* root_w = (const float*)d_in[3];
    const float* root_b = (const float*)d_in[4];
    const int*   e_src  = (const int*)d_in[5];
    const int*   e_dst  = (const int*)d_in[6];
    const int*   e_typ  = (const int*)d_in[7];
    const int*   n_typ  = (const int*)d_in[8];
    float* out = (float*)d_out;

    void *aggp = nullptr, *cntp = nullptr;
    cudaGetSymbolAddress(&aggp, g_agg);
    cudaGetSymbolAddress(&cntp, g_cnt);
    cudaMemsetAsync(aggp, 0, (size_t)N_TGT * NREL * CH * sizeof(float));
    cudaMemsetAsync(cntp, 0, (size_t)N_TGT * NREL * sizeof(float));

    scatter_kernel<<<N_EDGES / 8, 256>>>(x_src, e_src, e_dst, e_typ,
                                         (float*)aggp, (float*)cntp);

    gemm_mma_kernel<<<(N_TGT + 127) / 128, 256>>>(
        (const float*)aggp, (const float*)cntp, rel_w, x_tgt,
        root_w, root_b, n_typ, out);
}

// round 5
// speedup vs baseline: 2.8492x; 1.0071x over previous
#include <cuda_runtime.h>
#include <cstdint>

#define N_SRC   100000
#define N_TGT   50000
#define N_EDGES 600000
#define CH      128
#define NREL    7
#define NTYP    4
#define NSEG    11
#define NCHUNK  44          // NSEG * (128/32)

// GEMM tiling
#define TILE_M  64
#define SSTR    36                      // padded row stride (words)
#define A_WORDS (TILE_M * SSTR)         // 2304
#define B_WORDS (128 * SSTR)            // 4608
#define STAGE_WORDS (A_WORDS + B_WORDS) // 6912
#define NSTAGE  3
#define GSMEM_BYTES (NSTAGE * STAGE_WORDS * 4)   // 82944

// Scratch (allocation-free rule: __device__ globals)
__device__ float    g_agg[(size_t)N_TGT * NREL * CH];   // pre-normalized sums
__device__ float    g_cnt[N_TGT * NREL];
__device__ uint32_t g_wtf32[NSEG * CH * CH];            // tf32 weights, seg-major

__device__ __forceinline__ uint32_t to_tf32(float x) {
    uint32_t r;
    asm("cvt.rna.tf32.f32 %0, %1;" : "=r"(r) : "f"(x));
    return r;
}
__device__ __forceinline__ uint32_t smem_u32(const void* p) {
    uint32_t a;
    asm("{ .reg .u64 t; cvta.to.shared.u64 t, %1; cvt.u32.u64 %0, t; }" : "=r"(a) : "l"(p));
    return a;
}
__device__ __forceinline__ void cp16(uint32_t dst, const void* src, bool pred) {
    asm volatile("cp.async.ca.shared.global [%0], [%1], 16, %2;"
                 :: "r"(dst), "l"(src), "r"(pred ? 16 : 0) : "memory");
}
#define CP_COMMIT() asm volatile("cp.async.commit_group;" ::: "memory")
#define CP_WAIT(n)  asm volatile("cp.async.wait_group %0;" :: "n"(n) : "memory")

__device__ __forceinline__ void mma_tf32(float* c,
    uint32_t a0, uint32_t a1, uint32_t a2, uint32_t a3,
    uint32_t b0, uint32_t b1)
{
    asm volatile(
        "mma.sync.aligned.m16n8k8.row.col.f32.tf32.tf32.f32 "
        "{%0,%1,%2,%3}, {%4,%5,%6,%7}, {%8,%9}, {%0,%1,%2,%3};"
        : "+f"(c[0]), "+f"(c[1]), "+f"(c[2]), "+f"(c[3])
        : "r"(a0), "r"(a1), "r"(a2), "r"(a3), "r"(b0), "r"(b1));
}

// ---------------- kernel 0: weight pre-convert (rel_w ++ root_w -> tf32) ----
__global__ __launch_bounds__(256) void prep_weights(
    const float* __restrict__ relw, const float* __restrict__ rootw,
    uint32_t* __restrict__ wt)
{
    int i = blockIdx.x * 256 + threadIdx.x;          // float4 index
    const int NREL4 = NREL * CH * CH / 4;
    const int TOT4  = NSEG * CH * CH / 4;
    if (i >= TOT4) return;
    float4 v = (i < NREL4) ? ((const float4*)relw)[i]
                           : ((const float4*)rootw)[i - NREL4];
    uint4 w;
    w.x = to_tf32(v.x); w.y = to_tf32(v.y);
    w.z = to_tf32(v.z); w.w = to_tf32(v.w);
    ((uint4*)wt)[i] = w;
}

// ---------------- kernel 1: edge degree count ----------------
__global__ __launch_bounds__(256) void count_kernel(
    const int* __restrict__ edst, const int* __restrict__ etyp,
    float* __restrict__ cnt)
{
    int e = blockIdx.x * 256 + threadIdx.x;
    if (e >= N_EDGES) return;
    int d = __ldg(edst + e);
    int t = __ldg(etyp + e);
    asm volatile("red.global.add.f32 [%0], %1;"
                 :: "l"(cnt + d * NREL + t), "f"(1.0f) : "memory");
}

// ---------------- kernel 2: normalized edge scatter ----------------
__global__ __launch_bounds__(256) void scatter_kernel(
    const float* __restrict__ xs,
    const int* __restrict__ esrc, const int* __restrict__ edst,
    const int* __restrict__ etyp, const float* __restrict__ cnt,
    float* __restrict__ agg)
{
    int w = (blockIdx.x * 256 + threadIdx.x) >> 5;
    int lane = threadIdx.x & 31;
    if (w >= N_EDGES) return;
    int s = __ldg(esrc + w);
    int d = __ldg(edst + w);
    int t = __ldg(etyp + w);
    float inv = 1.0f / fmaxf(__ldg(cnt + d * NREL + t), 1.0f);
    float4 v = ((const float4*)(xs + ((size_t)s << 7)))[lane];
    v.x *= inv; v.y *= inv; v.z *= inv; v.w *= inv;
    float* base = agg + (((size_t)d * NREL + t) << 7) + (lane << 2);
    asm volatile("red.global.add.v4.f32 [%0], {%1,%2,%3,%4};"
                 :: "l"(base), "f"(v.x), "f"(v.y), "f"(v.z), "f"(v.w) : "memory");
}

// ---------------- kernel 3: tf32 mma.sync fused GEMM, cp.async pipeline ----
// out[g][c] = sum_{r<7} aggN[g][r] . rel_w[r][c]
//           + x_target[g] . root_w[type[g]][c] + root_b[type[g]][c]
// CTA: 64 rows x 128 cols, 8 warps 2x4 (32x32/warp, 2x4 m16n8k8 tiles).
// 3-stage cp.async double... triple buffer; weights pre-converted to tf32.
__global__ __launch_bounds__(256, 2) void gemm_mma_kernel(
    const float* __restrict__ agg, const uint32_t* __restrict__ wt,
    const float* __restrict__ xt, const float* __restrict__ rootb,
    const int* __restrict__ ttype, float* __restrict__ out)
{
    extern __shared__ uint32_t smw[];
    __shared__ int sTyp[TILE_M];

    const int tid = threadIdx.x;
    const int wid = tid >> 5;
    const int lid = tid & 31;
    const int wm = wid & 1;        // 32-row half
    const int wn = wid >> 1;       // 32-col quarter
    const int row0 = blockIdx.x * TILE_M;
    const uint32_t sb = smem_u32(smw);

    if (tid < TILE_M) {
        int g = row0 + tid;
        sTyp[tid] = (g < N_TGT) ? ttype[g] : -1;
    }
    __syncthreads();

    // ---- chunk issue: 2 A cp.async + 4 B cp.async per thread ----
    auto issue_chunk = [&](int ci, int stage) {
        int seg = ci >> 2;
        int k0  = (ci & 3) << 5;
        uint32_t aB = sb + stage * (STAGE_WORDS * 4);
        uint32_t bB = aB + A_WORDS * 4;
#pragma unroll
        for (int j = 0; j < 2; ++j) {
            int i = tid + (j << 8);            // 0..511
            int row = i >> 3, kv = i & 7;
            int g = row0 + row;
            bool ok = (g < N_TGT);
            int gc = ok ? g : 0;
            const float* src;
            if (seg < NREL) {
                src = agg + (((size_t)gc * NREL + seg) << 7) + k0 + (kv << 2);
            } else {
                ok = ok && (sTyp[row] == seg - NREL);
                src = xt + ((size_t)gc << 7) + k0 + (kv << 2);
            }
            cp16(aB + row * (SSTR * 4) + (kv << 4), src, ok);
        }
        const uint32_t* wsrc = wt + ((size_t)seg << 14) + k0;
#pragma unroll
        for (int j = 0; j < 4; ++j) {
            int i = tid + (j << 8);            // 0..1023
            int c = i >> 3, kv = i & 7;
            cp16(bB + c * (SSTR * 4) + (kv << 4), wsrc + (c << 7) + (kv << 2), true);
        }
    };

    float acc[2][4][4];
#pragma unroll
    for (int mi = 0; mi < 2; ++mi)
#pragma unroll
        for (int ni = 0; ni < 4; ++ni)
#pragma unroll
            for (int q = 0; q < 4; ++q) acc[mi][ni][q] = 0.0f;

    // prologue: fill all stages
#pragma unroll
    for (int p = 0; p < NSTAGE; ++p) { issue_chunk(p, p); CP_COMMIT(); }

    const int arow  = (wm << 5) + (lid >> 2);
    const int bcol0 = (wn << 5) + (lid >> 2);

    for (int ci = 0; ci < NCHUNK; ++ci) {
        int stage = ci % NSTAGE;
        CP_WAIT(NSTAGE - 1);           // chunk ci arrived (for this thread)
        __syncthreads();               // ...and for all threads
        const uint32_t* sw = smw + stage * STAGE_WORDS;
        const uint32_t* pA = sw + arow * SSTR;
        const uint32_t* pB = sw + A_WORDS + bcol0 * SSTR;
#pragma unroll
        for (int ks = 0; ks < 4; ++ks) {
            int kk = (ks << 3) + (lid & 3);
            uint32_t b[4][2];
#pragma unroll
            for (int ni = 0; ni < 4; ++ni) {
                b[ni][0] = pB[(ni << 3) * SSTR + kk];
                b[ni][1] = pB[(ni << 3) * SSTR + kk + 4];
            }
#pragma unroll
            for (int mi = 0; mi < 2; ++mi) {
                // A-fragment order: (r,k), (r+8,k), (r,k+4), (r+8,k+4)
                uint32_t a0 = to_tf32(__uint_as_float(pA[(mi << 4) * SSTR + kk]));
                uint32_t a1 = to_tf32(__uint_as_float(pA[((mi << 4) + 8) * SSTR + kk]));
                uint32_t a2 = to_tf32(__uint_as_float(pA[(mi << 4) * SSTR + kk + 4]));
                uint32_t a3 = to_tf32(__uint_as_float(pA[((mi << 4) + 8) * SSTR + kk + 4]));
#pragma unroll
                for (int ni = 0; ni < 4; ++ni)
                    mma_tf32(acc[mi][ni], a0, a1, a2, a3, b[ni][0], b[ni][1]);
            }
        }
        __syncthreads();               // all warps done with this stage
        if (ci + NSTAGE < NCHUNK) issue_chunk(ci + NSTAGE, stage);
        CP_COMMIT();                   // keep group accounting uniform
    }

    // ---- epilogue: bias + store ----
#pragma unroll
    for (int mi = 0; mi < 2; ++mi) {
#pragma unroll
        for (int half = 0; half < 2; ++half) {
            int row = (wm << 5) + (mi << 4) + (half << 3) + (lid >> 2);
            int g = row0 + row;
            if (g >= N_TGT) continue;
            int t = sTyp[row];
#pragma unroll
            for (int ni = 0; ni < 4; ++ni) {
                int col = (wn << 5) + (ni << 3) + ((lid & 3) << 1);
                float2 o;
                o.x = acc[mi][ni][half * 2 + 0] + rootb[(t << 7) + col];
                o.y = acc[mi][ni][half * 2 + 1] + rootb[(t << 7) + col + 1];
                *(float2*)(out + ((size_t)g << 7) + col) = o;
            }
        }
    }
}

extern "C" void kernel_launch(void* const* d_in, const int* in_sizes, int n_in,
                              void* d_out, int out_size)
{
    const float* x_src  = (const float*)d_in[0];
    const float* x_tgt  = (const float*)d_in[1];
    const float* rel_w  = (const float*)d_in[2];
    const float* root_w = (const float*)d_in[3];
    const float* root_b = (const float*)d_in[4];
    const int*   e_src  = (const int*)d_in[5];
    const int*   e_dst  = (const int*)d_in[6];
    const int*   e_typ  = (const int*)d_in[7];
    const int*   n_typ  = (const int*)d_in[8];
    float* out = (float*)d_out;

    void *aggp = nullptr, *cntp = nullptr, *wtp = nullptr;
    cudaGetSymbolAddress(&aggp, g_agg);
    cudaGetSymbolAddress(&cntp, g_cnt);
    cudaGetSymbolAddress(&wtp,  g_wtf32);
    cudaMemsetAsync(aggp, 0, (size_t)N_TGT * NREL * CH * sizeof(float));
    cudaMemsetAsync(cntp, 0, (size_t)N_TGT * NREL * sizeof(float));

    prep_weights<<<(NSEG * CH * CH / 4 + 255) / 256, 256>>>(rel_w, root_w, (uint32_t*)wtp);
    count_kernel<<<(N_EDGES + 255) / 256, 256>>>(e_dst, e_typ, (float*)cntp);
    scatter_kernel<<<N_EDGES / 8, 256>>>(x_src, e_src, e_dst, e_typ,
                                         (const float*)cntp, (float*)aggp);

    cudaFuncSetAttribute(gemm_mma_kernel,
                         cudaFuncAttributeMaxDynamicSharedMemorySize, GSMEM_BYTES);
    gemm_mma_kernel<<<(N_TGT + TILE_M - 1) / TILE_M, 256, GSMEM_BYTES>>>(
        (const float*)aggp, (const uint32_t*)wtp, x_tgt, root_b, n_typ, out);
}